// round 2
// baseline (speedup 1.0000x reference)
#include <cuda_runtime.h>

#define NN 50000
#define EE 800000
#define DD 64

// ---- scratch (static __device__ — no allocations allowed) ----
__device__ float    g_value[(size_t)EE * DD];   // LN'd value per edge (204.8 MB)
__device__ float    g_score[EE];                // score, then exp(score - max)
__device__ unsigned g_segmax[NN];               // order-encoded float max per dst
__device__ float    g_segsum[NN];               // softmax denominator per dst
__device__ float    g_accum[(size_t)NN * DD];   // pre-LN output accumulator

__device__ __forceinline__ float wsum(float v) {
#pragma unroll
    for (int o = 16; o; o >>= 1) v += __shfl_xor_sync(0xffffffffu, v, o);
    return v;
}

// monotonic float->unsigned encoding so atomicMax(unsigned) == float max
__device__ __forceinline__ unsigned enc_f(float x) {
    unsigned b = __float_as_uint(x);
    return (b & 0x80000000u) ? ~b : (b | 0x80000000u);
}
__device__ __forceinline__ float dec_f(unsigned u) {
    unsigned b = (u & 0x80000000u) ? (u ^ 0x80000000u) : ~u;
    return __uint_as_float(b);
}

__global__ void init_kernel() {
    int i = blockIdx.x * blockDim.x + threadIdx.x;
    int stride = gridDim.x * blockDim.x;
    for (int j = i; j < NN * DD; j += stride) g_accum[j] = 0.f;
    for (int j = i; j < NN; j += stride) { g_segsum[j] = 0.f; g_segmax[j] = 0u; }
}

// One warp per edge; lane handles dims (2*lane, 2*lane+1).
// Computes KEY (-> score, segmax) and VALUE (-> g_value) in one pass so each
// of the 12 big E x D tensors is read from HBM exactly once.
__global__ void __launch_bounds__(256) edge_kernel(
    const float* __restrict__ feat, const float* __restrict__ query,
    const int* __restrict__ src, const int* __restrict__ dst,
    const float* __restrict__ skw, const float* __restrict__ skb,
    const float* __restrict__ dkw, const float* __restrict__ dkb,
    const float* __restrict__ ekw, const float* __restrict__ ekb,
    const float* __restrict__ svw, const float* __restrict__ svb,
    const float* __restrict__ dvw, const float* __restrict__ dvb,
    const float* __restrict__ evw, const float* __restrict__ evb,
    const float* __restrict__ kgamma, const float* __restrict__ kbeta,
    const float* __restrict__ vgamma, const float* __restrict__ vbeta)
{
    int e = blockIdx.x * 8 + (threadIdx.x >> 5);
    if (e >= EE) return;
    int lane = threadIdx.x & 31;
    int d0 = lane * 2;
    int s = src[e], t = dst[e];

    float2 u = *(const float2*)(feat + (size_t)s * DD + d0);   // L2-resident gather
    float2 v = *(const float2*)(feat + (size_t)t * DD + d0);
    size_t base = (size_t)e * DD + d0;

    // ---------------- key branch -> score ----------------
    {
        float2 w1 = *(const float2*)(skw + base), b1 = *(const float2*)(skb + base);
        float2 w2 = *(const float2*)(dkw + base), b2 = *(const float2*)(dkb + base);
        float2 w3 = *(const float2*)(ekw + base), b3 = *(const float2*)(ekb + base);
        float hx = fmaf(u.x, w1.x, b1.x) + fmaf(v.x, w2.x, b2.x);
        float hy = fmaf(u.y, w1.y, b1.y) + fmaf(v.y, w2.y, b2.y);
        hx = fmaf(fmaxf(hx, 0.f), w3.x, b3.x);
        hy = fmaf(fmaxf(hy, 0.f), w3.y, b3.y);
        float mu  = wsum(hx + hy) * (1.f / DD);
        float dx = hx - mu, dy = hy - mu;
        float var = wsum(dx * dx + dy * dy) * (1.f / DD);
        float inv = rsqrtf(var + 1e-5f);
        float2 g  = *(const float2*)(kgamma + d0);
        float2 bb = *(const float2*)(kbeta + d0);
        float kx = fmaf(dx * inv, g.x, bb.x);
        float ky = fmaf(dy * inv, g.y, bb.y);
        float2 q = *(const float2*)(query + (size_t)t * DD + d0);
        float sc = wsum(kx * q.x + ky * q.y);
        if (lane == 0) {
            g_score[e] = sc;
            atomicMax(&g_segmax[t], enc_f(sc));
        }
    }

    // ---------------- value branch -> g_value ----------------
    {
        float2 w1 = *(const float2*)(svw + base), b1 = *(const float2*)(svb + base);
        float2 w2 = *(const float2*)(dvw + base), b2 = *(const float2*)(dvb + base);
        float2 w3 = *(const float2*)(evw + base), b3 = *(const float2*)(evb + base);
        float hx = fmaf(u.x, w1.x, b1.x) + fmaf(v.x, w2.x, b2.x);
        float hy = fmaf(u.y, w1.y, b1.y) + fmaf(v.y, w2.y, b2.y);
        hx = fmaf(fmaxf(hx, 0.f), w3.x, b3.x);
        hy = fmaf(fmaxf(hy, 0.f), w3.y, b3.y);
        float mu  = wsum(hx + hy) * (1.f / DD);
        float dx = hx - mu, dy = hy - mu;
        float var = wsum(dx * dx + dy * dy) * (1.f / DD);
        float inv = rsqrtf(var + 1e-5f);
        float2 g  = *(const float2*)(vgamma + d0);
        float2 bb = *(const float2*)(vbeta + d0);
        float vx = fmaf(dx * inv, g.x, bb.x);
        float vy = fmaf(dy * inv, g.y, bb.y);
        *(float2*)(g_value + base) = make_float2(vx, vy);
    }
}

// exp(score - segmax[dst]) and segment sum
__global__ void softmax_kernel(const int* __restrict__ dst) {
    int e = blockIdx.x * blockDim.x + threadIdx.x;
    if (e >= EE) return;
    int t = dst[e];
    float m = dec_f(g_segmax[t]);
    float ex = expf(g_score[e] - m);
    g_score[e] = ex;
    atomicAdd(&g_segsum[t], ex);
}

// attn = ex / segsum[dst]; msg = value * attn; vector-red into g_accum.
// 16 threads per edge, float4 per thread.
__global__ void __launch_bounds__(256) scatter_kernel(const int* __restrict__ dst,
                                                      float* __restrict__ attn_out) {
    long idx = (long)blockIdx.x * 256 + threadIdx.x;
    int e   = (int)(idx >> 4);
    int sub = (int)(idx & 15);
    if (e >= EE) return;
    int t = dst[e];
    float a = g_score[e] / g_segsum[t];
    if (sub == 0) attn_out[e] = a;
    size_t base = (size_t)e * DD + sub * 4;
    float4 val = *(const float4*)(g_value + base);
    float4 m = make_float4(val.x * a, val.y * a, val.z * a, val.w * a);
    atomicAdd((float4*)(g_accum + (size_t)t * DD + sub * 4), m);
}

// final LayerNorm over accumulated node features; warp per node
__global__ void __launch_bounds__(256) node_ln_kernel(const float* __restrict__ agamma,
                                                      const float* __restrict__ abeta,
                                                      float* __restrict__ out) {
    int n = blockIdx.x * 8 + (threadIdx.x >> 5);
    if (n >= NN) return;
    int lane = threadIdx.x & 31;
    int d0 = lane * 2;
    float2 a = *(const float2*)(g_accum + (size_t)n * DD + d0);
    float mu  = wsum(a.x + a.y) * (1.f / DD);
    float dx = a.x - mu, dy = a.y - mu;
    float var = wsum(dx * dx + dy * dy) * (1.f / DD);
    float inv = rsqrtf(var + 1e-5f);
    float2 g = *(const float2*)(agamma + d0);
    float2 b = *(const float2*)(abeta + d0);
    *(float2*)(out + (size_t)n * DD + d0) =
        make_float2(fmaf(dx * inv, g.x, b.x), fmaf(dy * inv, g.y, b.y));
}

extern "C" void kernel_launch(void* const* d_in, const int* in_sizes, int n_in,
                              void* d_out, int out_size) {
    const float* feat  = (const float*)d_in[0];
    const float* query = (const float*)d_in[1];
    const int*   src   = (const int*)d_in[2];
    const int*   dst   = (const int*)d_in[3];
    const float* skw = (const float*)d_in[4],  *skb = (const float*)d_in[5];
    const float* dkw = (const float*)d_in[6],  *dkb = (const float*)d_in[7];
    const float* ekw = (const float*)d_in[8],  *ekb = (const float*)d_in[9];
    const float* svw = (const float*)d_in[10], *svb = (const float*)d_in[11];
    const float* dvw = (const float*)d_in[12], *dvb = (const float*)d_in[13];
    const float* evw = (const float*)d_in[14], *evb = (const float*)d_in[15];
    const float* kg  = (const float*)d_in[16], *kb  = (const float*)d_in[17];
    const float* vg  = (const float*)d_in[18], *vb  = (const float*)d_in[19];
    const float* ag  = (const float*)d_in[20], *ab  = (const float*)d_in[21];

    float* out  = (float*)d_out;                 // [N, D]
    float* attn = out + (size_t)NN * DD;         // [E, 1]

    init_kernel<<<1024, 256>>>();
    edge_kernel<<<(EE + 7) / 8, 256>>>(feat, query, src, dst,
                                       skw, skb, dkw, dkb, ekw, ekb,
                                       svw, svb, dvw, dvb, evw, evb,
                                       kg, kb, vg, vb);
    softmax_kernel<<<(EE + 255) / 256, 256>>>(dst);
    scatter_kernel<<<((long)EE * 16 + 255) / 256, 256>>>(dst, attn);
    node_ln_kernel<<<(NN + 7) / 8, 256>>>(ag, ab, out);
}